// round 1
// baseline (speedup 1.0000x reference)
#include <cuda_runtime.h>

// Scratch for h_neigh: 100000 x 128 f32 (static __device__ global — no allocation)
static __device__ float g_hneigh[100000 * 128];

// ---------------------------------------------------------------------------
// Kernel 1: aggregate. One warp per dst node.
// lane l handles features [4l, 4l+4): p = l>>1, half = l&1 (w offset 0 or 4).
// Gathers 16 codes per edge (64B, L2-resident table), decodes from codebook
// (128KB, L1-resident via __ldg), accumulates, divides by degree.
// ---------------------------------------------------------------------------
__global__ __launch_bounds__(256) void agg_kernel(
    const int* __restrict__ codes,
    const int* __restrict__ indices,
    const int* __restrict__ indptr,
    const float* __restrict__ codebook,
    int n_dst)
{
    int warp = blockIdx.x * (blockDim.x >> 5) + (threadIdx.x >> 5);
    if (warp >= n_dst) return;
    int lane = threadIdx.x & 31;
    int p    = lane >> 1;
    int half = lane & 1;

    int e0  = indptr[warp];
    int e1  = indptr[warp + 1];
    int deg = e1 - e0;

    const float4* cb4 = (const float4*)codebook;
    // float4 index for (p, c, half): ((p*256 + c)*8 + half*4)/4 = p*512 + c*2 + half
    int pbase = p * 512 + half;

    float4 acc = make_float4(0.f, 0.f, 0.f, 0.f);

    if (deg == 16) {
        // fast path: batch the index loads, then all code gathers (MLP=16),
        // then all codebook loads (MLP=16)
        int myidx = indices[e0 + (lane & 15)];
        int c[16];
        #pragma unroll
        for (int e = 0; e < 16; e++) {
            int src = __shfl_sync(0xffffffffu, myidx, e);
            c[e] = __ldg(&codes[src * 16 + p]);
        }
        #pragma unroll
        for (int e = 0; e < 16; e++) {
            float4 v = __ldg(&cb4[pbase + c[e] * 2]);
            acc.x += v.x; acc.y += v.y; acc.z += v.z; acc.w += v.w;
        }
    } else {
        for (int e = e0; e < e1; e++) {
            int src = __ldg(&indices[e]);
            int cc  = __ldg(&codes[src * 16 + p]);
            float4 v = __ldg(&cb4[pbase + cc * 2]);
            acc.x += v.x; acc.y += v.y; acc.z += v.z; acc.w += v.w;
        }
    }

    float inv = 1.0f / (float)(deg > 1 ? deg : 1);
    acc.x *= inv; acc.y *= inv; acc.z *= inv; acc.w *= inv;
    *(float4*)&g_hneigh[(size_t)warp * 128 + lane * 4] = acc;
}

// ---------------------------------------------------------------------------
// Kernel 2: out[M,128] = h_neigh @ Wn^T + h_self @ Ws^T + b
// Tiled SIMT f32 GEMM: block tile 128x128 (full N), 256 threads, 8x8 per
// thread, K chunk 8, smem padded to 132 to kill store bank conflicts.
// Two K-passes (neigh matrix, self matrix) accumulate into the same regs.
// ---------------------------------------------------------------------------
#define BM 128
#define KC 8

__global__ __launch_bounds__(256) void gemm_kernel(
    const float* __restrict__ h_self,
    const float* __restrict__ Wn,
    const float* __restrict__ Ws,
    const float* __restrict__ bias,
    float* __restrict__ out,
    int M)
{
    __shared__ float sX[KC][132];
    __shared__ float sW[KC][132];

    int t  = threadIdx.x;
    int tx = t & 15;       // output col group (8 cols)
    int ty = t >> 4;       // output row group (8 rows)
    int row0 = blockIdx.x * BM;

    float acc[8][8];
    #pragma unroll
    for (int i = 0; i < 8; i++)
        #pragma unroll
        for (int j = 0; j < 8; j++)
            acc[i][j] = 0.f;

    int lm = t >> 1;        // 0..127: row (for X) / n (for W) being loaded
    int lk = (t & 1) * 4;   // 0 or 4: k offset within chunk

    int r = row0 + lm;
    if (r >= M) r = M - 1;  // clamp; rows >= M are computed but never stored

    #pragma unroll 1
    for (int pass = 0; pass < 2; pass++) {
        const float* X = pass ? h_self : g_hneigh;
        const float* W = pass ? Ws : Wn;

        #pragma unroll 1
        for (int kk = 0; kk < 128; kk += KC) {
            float4 xv = __ldg((const float4*)&X[(size_t)r * 128 + kk + lk]);
            float4 wv = __ldg((const float4*)&W[lm * 128 + kk + lk]);
            __syncthreads();   // previous chunk's compute done before overwrite
            sX[lk + 0][lm] = xv.x; sX[lk + 1][lm] = xv.y;
            sX[lk + 2][lm] = xv.z; sX[lk + 3][lm] = xv.w;
            sW[lk + 0][lm] = wv.x; sW[lk + 1][lm] = wv.y;
            sW[lk + 2][lm] = wv.z; sW[lk + 3][lm] = wv.w;
            __syncthreads();

            #pragma unroll
            for (int k = 0; k < KC; k++) {
                float a[8], b[8];
                *(float4*)&a[0] = *(const float4*)&sX[k][ty * 8];
                *(float4*)&a[4] = *(const float4*)&sX[k][ty * 8 + 4];
                *(float4*)&b[0] = *(const float4*)&sW[k][tx * 8];
                *(float4*)&b[4] = *(const float4*)&sW[k][tx * 8 + 4];
                #pragma unroll
                for (int i = 0; i < 8; i++)
                    #pragma unroll
                    for (int j = 0; j < 8; j++)
                        acc[i][j] += a[i] * b[j];
            }
        }
    }

    // epilogue: add bias, store
    float bj[8];
    *(float4*)&bj[0] = __ldg((const float4*)&bias[tx * 8]);
    *(float4*)&bj[4] = __ldg((const float4*)&bias[tx * 8 + 4]);

    #pragma unroll
    for (int i = 0; i < 8; i++) {
        int rr = row0 + ty * 8 + i;
        if (rr < M) {
            float4 o0, o1;
            o0.x = acc[i][0] + bj[0]; o0.y = acc[i][1] + bj[1];
            o0.z = acc[i][2] + bj[2]; o0.w = acc[i][3] + bj[3];
            o1.x = acc[i][4] + bj[4]; o1.y = acc[i][5] + bj[5];
            o1.z = acc[i][6] + bj[6]; o1.w = acc[i][7] + bj[7];
            *(float4*)&out[(size_t)rr * 128 + tx * 8]     = o0;
            *(float4*)&out[(size_t)rr * 128 + tx * 8 + 4] = o1;
        }
    }
}

// ---------------------------------------------------------------------------
// Launch
// inputs: 0 codes[i32], 1 indices[i32], 2 indptr[i32], 3 h_self[f32],
//         4 codebook[f32], 5 W_neigh[f32], 6 W_self[f32], 7 b_self[f32]
// ---------------------------------------------------------------------------
extern "C" void kernel_launch(void* const* d_in, const int* in_sizes, int n_in,
                              void* d_out, int out_size)
{
    const int*   codes    = (const int*)d_in[0];
    const int*   indices  = (const int*)d_in[1];
    const int*   indptr   = (const int*)d_in[2];
    const float* h_self   = (const float*)d_in[3];
    const float* codebook = (const float*)d_in[4];
    const float* Wn       = (const float*)d_in[5];
    const float* Ws       = (const float*)d_in[6];
    const float* b        = (const float*)d_in[7];
    float*       out      = (float*)d_out;

    int n_dst = in_sizes[2] - 1;   // indptr has n_dst+1 entries

    int warps_per_block = 256 / 32;
    int agg_blocks = (n_dst + warps_per_block - 1) / warps_per_block;
    agg_kernel<<<agg_blocks, 256>>>(codes, indices, indptr, codebook, n_dst);

    int gemm_blocks = (n_dst + BM - 1) / BM;
    gemm_kernel<<<gemm_blocks, 256>>>(h_self, Wn, Ws, b, out, n_dst);
}

// round 3
// speedup vs baseline: 1.7432x; 1.7432x over previous
#include <cuda_runtime.h>
#include <cstdint>

// Scratch for h_neigh: 100000 x 128 f32 (static __device__ global — no allocation)
static __device__ float g_hneigh[100000 * 128];

__device__ __forceinline__ uint32_t f2tf32(float x) {
    uint32_t d;
    asm("cvt.rna.tf32.f32 %0, %1;" : "=r"(d) : "f"(x));
    return d;
}

__device__ __forceinline__ void mma_tf32(float* d, const uint32_t* a, const uint32_t* b) {
    asm volatile(
        "mma.sync.aligned.m16n8k8.row.col.f32.tf32.tf32.f32 "
        "{%0,%1,%2,%3}, {%4,%5,%6,%7}, {%8,%9}, {%0,%1,%2,%3};"
        : "+f"(d[0]), "+f"(d[1]), "+f"(d[2]), "+f"(d[3])
        : "r"(a[0]), "r"(a[1]), "r"(a[2]), "r"(a[3]), "r"(b[0]), "r"(b[1]));
}

// ===========================================================================
// Kernel 1: aggregate. One warp per dst node.
// ===========================================================================
__global__ __launch_bounds__(256) void agg_kernel(
    const int* __restrict__ codes,
    const int* __restrict__ indices,
    const int* __restrict__ indptr,
    const float* __restrict__ codebook,
    int n_dst)
{
    int warp = blockIdx.x * (blockDim.x >> 5) + (threadIdx.x >> 5);
    if (warp >= n_dst) return;
    int lane = threadIdx.x & 31;
    int p    = lane >> 1;
    int half = lane & 1;

    int e0  = indptr[warp];
    int e1  = indptr[warp + 1];
    int deg = e1 - e0;

    const float4* cb4 = (const float4*)codebook;
    int pbase = p * 512 + half;

    float4 acc = make_float4(0.f, 0.f, 0.f, 0.f);

    if (deg == 16) {
        int myidx = indices[e0 + (lane & 15)];
        int c[16];
        #pragma unroll
        for (int e = 0; e < 16; e++) {
            int src = __shfl_sync(0xffffffffu, myidx, e);
            c[e] = __ldg(&codes[src * 16 + p]);
        }
        #pragma unroll
        for (int e = 0; e < 16; e++) {
            float4 v = __ldg(&cb4[pbase + c[e] * 2]);
            acc.x += v.x; acc.y += v.y; acc.z += v.z; acc.w += v.w;
        }
    } else {
        for (int e = e0; e < e1; e++) {
            int src = __ldg(&indices[e]);
            int cc  = __ldg(&codes[src * 16 + p]);
            float4 v = __ldg(&cb4[pbase + cc * 2]);
            acc.x += v.x; acc.y += v.y; acc.z += v.z; acc.w += v.w;
        }
    }

    float inv = 1.0f / (float)(deg > 1 ? deg : 1);
    acc.x *= inv; acc.y *= inv; acc.z *= inv; acc.w *= inv;
    *(float4*)&g_hneigh[(size_t)warp * 128 + lane * 4] = acc;
}

// ===========================================================================
// Kernel 2: tf32 mma.sync GEMM
//   out[M,128] = h_neigh @ Wn^T + h_self @ Ws^T + b
// CTA tile 128x128, 8 warps (2x4), warp tile 64x32 (4x4 of m16n8k8).
// K=256 as 16 chunks of 16 (chunks 0-7: h_neigh/Wn, 8-15: h_self/Ws),
// double-buffered smem, row stride 20 floats (conflict-free fragment LDS).
// ===========================================================================
#define KC 16
#define SSTRIDE 20   // floats per smem row (16 data + 4 pad); (20g+c)%32 distinct

__global__ __launch_bounds__(256) void mma_gemm(
    const float* __restrict__ h_self,
    const float* __restrict__ Wn,
    const float* __restrict__ Ws,
    const float* __restrict__ bias,
    float* __restrict__ out,
    int M)
{
    __shared__ float sA[2][128 * SSTRIDE];
    __shared__ float sB[2][128 * SSTRIDE];

    const int t    = threadIdx.x;
    const int lane = t & 31;
    const int wid  = t >> 5;
    const int wm   = wid >> 2;      // 0..1 : 64-row band
    const int wn   = wid & 3;       // 0..3 : 32-col band
    const int g    = lane >> 2;     // group id 0..7
    const int c    = lane & 3;      // thread-in-group 0..3
    const int row0 = blockIdx.x * 128;

    // loader mapping: thread covers rows (t>>2) and (t>>2)+64, float4 col t&3
    const int lrow = t >> 2;
    const int lcq  = t & 3;

    float d[4][4][4];
    #pragma unroll
    for (int mt = 0; mt < 4; mt++)
        #pragma unroll
        for (int nt = 0; nt < 4; nt++)
            #pragma unroll
            for (int i = 0; i < 4; i++)
                d[mt][nt][i] = 0.f;

    float4 pa[2], pb[2];

    // ---- prefetch + store chunk 0
    {
        const float* X = g_hneigh;
        const float* W = Wn;
        #pragma unroll
        for (int i = 0; i < 2; i++) {
            int row = lrow + i * 64;
            int r = row0 + row; if (r >= M) r = M - 1;
            pa[i] = __ldg((const float4*)&X[(size_t)r * 128 + lcq * 4]);
            pb[i] = __ldg((const float4*)&W[row * 128 + lcq * 4]);
        }
        #pragma unroll
        for (int i = 0; i < 2; i++) {
            int row = lrow + i * 64;
            *(uint4*)&sA[0][row * SSTRIDE + lcq * 4] =
                make_uint4(f2tf32(pa[i].x), f2tf32(pa[i].y), f2tf32(pa[i].z), f2tf32(pa[i].w));
            *(uint4*)&sB[0][row * SSTRIDE + lcq * 4] =
                make_uint4(f2tf32(pb[i].x), f2tf32(pb[i].y), f2tf32(pb[i].z), f2tf32(pb[i].w));
        }
    }

    #pragma unroll 1
    for (int ck = 0; ck < 16; ck++) {
        const int s = ck & 1;
        __syncthreads();

        // prefetch next chunk from gmem
        if (ck < 15) {
            int nk = ck + 1;
            const float* X = (nk < 8) ? g_hneigh : h_self;
            const float* W = (nk < 8) ? Wn : Ws;
            int koff = (nk & 7) * KC;
            #pragma unroll
            for (int i = 0; i < 2; i++) {
                int row = lrow + i * 64;
                int r = row0 + row; if (r >= M) r = M - 1;
                pa[i] = __ldg((const float4*)&X[(size_t)r * 128 + koff + lcq * 4]);
                pb[i] = __ldg((const float4*)&W[row * 128 + koff + lcq * 4]);
            }
        }

        // compute on stage s: 2 k-steps of 8
        #pragma unroll
        for (int ks = 0; ks < 2; ks++) {
            const int kb = ks * 8;
            uint32_t a[4][4], b[4][2];
            #pragma unroll
            for (int mt = 0; mt < 4; mt++) {
                int base = (wm * 64 + mt * 16 + g) * SSTRIDE + kb + c;
                a[mt][0] = __float_as_uint(sA[s][base]);
                a[mt][1] = __float_as_uint(sA[s][base + 8 * SSTRIDE]);
                a[mt][2] = __float_as_uint(sA[s][base + 4]);
                a[mt][3] = __float_as_uint(sA[s][base + 8 * SSTRIDE + 4]);
            }
            #pragma unroll
            for (int nt = 0; nt < 4; nt++) {
                int base = (wn * 32 + nt * 8 + g) * SSTRIDE + kb + c;
                b[nt][0] = __float_as_uint(sB[s][base]);
                b[nt][1] = __float_as_uint(sB[s][base + 4]);
            }
            #pragma unroll
            for (int mt = 0; mt < 4; mt++)
                #pragma unroll
                for (int nt = 0; nt < 4; nt++)
                    mma_tf32(d[mt][nt], a[mt], b[nt]);
        }

        // stage the prefetched chunk into the other buffer
        if (ck < 15) {
            const int s2 = (ck + 1) & 1;
            #pragma unroll
            for (int i = 0; i < 2; i++) {
                int row = lrow + i * 64;
                *(uint4*)&sA[s2][row * SSTRIDE + lcq * 4] =
                    make_uint4(f2tf32(pa[i].x), f2tf32(pa[i].y), f2tf32(pa[i].z), f2tf32(pa[i].w));
                *(uint4*)&sB[s2][row * SSTRIDE + lcq * 4] =
                    make_uint4(f2tf32(pb[i].x), f2tf32(pb[i].y), f2tf32(pb[i].z), f2tf32(pb[i].w));
            }
        }
    }

    // ---- epilogue: bias + store
    #pragma unroll
    for (int nt = 0; nt < 4; nt++) {
        int col = wn * 32 + nt * 8 + 2 * c;
        float2 bv = __ldg((const float2*)&bias[col]);
        #pragma unroll
        for (int mt = 0; mt < 4; mt++) {
            int row = row0 + wm * 64 + mt * 16 + g;
            if (row < M) {
                float2 o; o.x = d[mt][nt][0] + bv.x; o.y = d[mt][nt][1] + bv.y;
                *(float2*)&out[(size_t)row * 128 + col] = o;
            }
            if (row + 8 < M) {
                float2 o; o.x = d[mt][nt][2] + bv.x; o.y = d[mt][nt][3] + bv.y;
                *(float2*)&out[(size_t)(row + 8) * 128 + col] = o;
            }
        }
    }
}

// ===========================================================================
// Launch
// inputs: 0 codes[i32], 1 indices[i32], 2 indptr[i32], 3 h_self[f32],
//         4 codebook[f32], 5 W_neigh[f32], 6 W_self[f32], 7 b_self[f32]
// ===========================================================================
extern "C" void kernel_launch(void* const* d_in, const int* in_sizes, int n_in,
                              void* d_out, int out_size)
{
    const int*   codes    = (const int*)d_in[0];
    const int*   indices  = (const int*)d_in[1];
    const int*   indptr   = (const int*)d_in[2];
    const float* h_self   = (const float*)d_in[3];
    const float* codebook = (const float*)d_in[4];
    const float* Wn       = (const float*)d_in[5];
    const float* Ws       = (const float*)d_in[6];
    const float* b        = (const float*)d_in[7];
    float*       out      = (float*)d_out;

    int n_dst = in_sizes[2] - 1;

    int warps_per_block = 256 / 32;
    int agg_blocks = (n_dst + warps_per_block - 1) / warps_per_block;
    agg_kernel<<<agg_blocks, 256>>>(codes, indices, indptr, codebook, n_dst);

    int tiles = (n_dst + 127) / 128;
    mma_gemm<<<tiles, 256>>>(h_self, Wn, Ws, b, out, n_dst);
}